// round 7
// baseline (speedup 1.0000x reference)
#include <cuda_runtime.h>
#include <math.h>

#define BB 4
#define NN 512
#define DD 128
#define TAU_INV 2.0f
#define EPSF 1e-9f

#define TI 16            // i rows per k_main block
#define JS 4             // j splits
#define JR (NN/JS)       // 128 j's per block
#define TJ 32            // j tile staged in shared

// k_proj tiles
#define PBM 32
#define PBN 64
#define PBK 32
// k_epi tiles
#define EBM 32
#define EBN 32
#define EBK 32
#define APAD 2           // row stride (32+2)*4B = 136B, 8B-aligned (float2 LDS only)

// ---------------- scratch ----------------
__device__ float g_sj[BB * NN * DD];          // (ES@Wp+bp)@W1_src + Bc_s
__device__ float g_ti[BB * NN * DD];          // (ES@Wp+bp)@W1_tgt + Bc_t (b1 folded)
__device__ float g_v [JS * BB * NN * DD];     // partial v per j-split (4 MB)
__device__ float g_Wc[DD * 256];              // combined weights [d][col], col<128 src
__device__ float g_Bc[256];                   // combined bias

// ---------------- packed f32x2 helpers ----------------
__device__ __forceinline__ void fma2acc(unsigned long long& acc,
                                        unsigned long long a, unsigned long long b) {
    asm("fma.rn.f32x2 %0, %1, %2, %0;" : "+l"(acc) : "l"(a), "l"(b));
}
__device__ __forceinline__ unsigned long long bcast2(float a) {
    unsigned long long r;
    asm("mov.b64 %0, {%1, %1};" : "=l"(r) : "f"(a));
    return r;
}
__device__ __forceinline__ float2 unpack2(unsigned long long v) {
    float2 r;
    asm("mov.b64 {%0, %1}, %2;" : "=f"(r.x), "=f"(r.y) : "l"(v));
    return r;
}
// acc += a * relu(s + t), 4 lanes (2 b64 packs)
__device__ __forceinline__ void relu_mad4(unsigned long long& acc0, unsigned long long& acc1,
                                          unsigned long long s0, unsigned long long s1,
                                          unsigned long long t0, unsigned long long t1,
                                          unsigned long long a2)
{
    asm("{\n\t"
        ".reg .b64 x0, x1;\n\t"
        ".reg .f32 l0, h0, l1, h1;\n\t"
        "add.rn.f32x2 x0, %2, %4;\n\t"
        "add.rn.f32x2 x1, %3, %5;\n\t"
        "mov.b64 {l0, h0}, x0;\n\t"
        "mov.b64 {l1, h1}, x1;\n\t"
        "max.f32 l0, l0, 0f00000000;\n\t"
        "max.f32 h0, h0, 0f00000000;\n\t"
        "max.f32 l1, l1, 0f00000000;\n\t"
        "max.f32 h1, h1, 0f00000000;\n\t"
        "mov.b64 x0, {l0, h0};\n\t"
        "mov.b64 x1, {l1, h1};\n\t"
        "fma.rn.f32x2 %0, x0, %6, %0;\n\t"
        "fma.rn.f32x2 %1, x1, %6, %1;\n\t"
        "}"
        : "+l"(acc0), "+l"(acc1)
        : "l"(s0), "l"(s1), "l"(t0), "l"(t1), "l"(a2));
}

// ============ K0: Wc = Wp @ [W1s|W1t];  Bc = bp @ [W1s|W1t] (+b1 tgt half) ============
__global__ void __launch_bounds__(256) k_combine(const float* __restrict__ Wp,
                                                 const float* __restrict__ bp,
                                                 const float* __restrict__ W1,
                                                 const float* __restrict__ b1)
{
    __shared__ float wp[DD];
    int col  = threadIdx.x;          // 0..255
    int d    = blockIdx.x;           // 0..128 (last block: biases)
    int half = col >> 7;
    int m    = col & 127;
    const float* base = W1 + (size_t)(half ? DD * DD : 0) + m;

    if (d < DD) {
        if (col < DD) wp[col] = Wp[d * DD + col];
        __syncthreads();
        float acc = 0.f;
        #pragma unroll 8
        for (int k = 0; k < DD; k++) acc += wp[k] * base[(size_t)k * DD];
        g_Wc[d * 256 + col] = acc;
    } else {
        float acc = half ? b1[m] : 0.f;
        #pragma unroll 8
        for (int k = 0; k < DD; k++) acc += bp[k] * base[(size_t)k * DD];
        g_Bc[col] = acc;
    }
}

// ============ K1: tiled GEMM: [s|t] = ES @ Wc + Bc ============
// grid (2048/32, 256/64) = (64,4) = 256 blocks; micro-tile 2 rows x 4 cols (packed).
__global__ void __launch_bounds__(256) k_proj(const float* __restrict__ ES)
{
    __shared__ float sE[PBK][PBM + APAD];   // transposed: sE[k][row]
    __shared__ float sW[PBK][PBN];

    int tid = threadIdx.x;
    int tx  = tid & 15;                  // cols tx*4..tx*4+3
    int ty  = tid >> 4;                  // rows ty*2, ty*2+1
    int r0  = blockIdx.x * PBM;
    int c0  = blockIdx.y * PBN;

    int lrow = tid >> 3;                 // 0..31
    int lk4  = tid & 7;                  // 0..7
    int wk   = tid >> 4;                 // 0..15 (+16)
    int wc4  = tid & 15;                 // 0..15

    float4 eA, wB[2];
    {
        eA    = *(const float4*)&ES[(size_t)(r0 + lrow) * DD + lk4 * 4];
        const float* wpg = g_Wc + c0;
        wB[0] = *(const float4*)&wpg[(wk     ) * 256 + wc4 * 4];
        wB[1] = *(const float4*)&wpg[(wk + 16) * 256 + wc4 * 4];
    }

    unsigned long long acc[2][2];
    acc[0][0] = acc[0][1] = acc[1][0] = acc[1][1] = 0ull;

    for (int kt = 0; kt < DD; kt += PBK) {
        if (kt) __syncthreads();
        sE[lk4 * 4 + 0][lrow] = eA.x;
        sE[lk4 * 4 + 1][lrow] = eA.y;
        sE[lk4 * 4 + 2][lrow] = eA.z;
        sE[lk4 * 4 + 3][lrow] = eA.w;
        *(float4*)&sW[wk][wc4 * 4]      = wB[0];
        *(float4*)&sW[wk + 16][wc4 * 4] = wB[1];
        __syncthreads();

        if (kt + PBK < DD) {
            eA    = *(const float4*)&ES[(size_t)(r0 + lrow) * DD + (kt + PBK) + lk4 * 4];
            const float* wpg = g_Wc + c0 + (size_t)(kt + PBK) * 256;
            wB[0] = *(const float4*)&wpg[(wk     ) * 256 + wc4 * 4];
            wB[1] = *(const float4*)&wpg[(wk + 16) * 256 + wc4 * 4];
        }

        #pragma unroll 8
        for (int k = 0; k < PBK; k++) {
            float2 e2 = *(const float2*)&sE[k][ty * 2];
            ulonglong2 w2 = *(const ulonglong2*)&sW[k][tx * 4];
            unsigned long long e0 = bcast2(e2.x);
            unsigned long long e1 = bcast2(e2.y);
            fma2acc(acc[0][0], e0, w2.x); fma2acc(acc[0][1], e0, w2.y);
            fma2acc(acc[1][0], e1, w2.x); fma2acc(acc[1][1], e1, w2.y);
        }
    }

    float4 bias = *(const float4*)&g_Bc[c0 + tx * 4];
    float* dst = (c0 < DD) ? g_sj : g_ti;
    int    mc  = (c0 < DD) ? c0 : (c0 - DD);
    #pragma unroll
    for (int r = 0; r < 2; r++) {
        int row = r0 + ty * 2 + r;
        float2 p0 = unpack2(acc[r][0]);
        float2 p1 = unpack2(acc[r][1]);
        float4 o;
        o.x = p0.x + bias.x; o.y = p0.y + bias.y;
        o.z = p1.x + bias.z; o.w = p1.y + bias.w;
        *(float4*)&dst[(size_t)row * DD + mc + tx * 4] = o;
    }
}

// ============ K2: fused gumbel-softmax + partial message aggregation ============
__global__ void __launch_bounds__(256, 4) k_main(const float* __restrict__ EL,
                                                 const float* __restrict__ UN,
                                                 float* __restrict__ out_A)
{
    __shared__ float sA[TI * JR];    // 8 KB
    __shared__ float sS[TJ * DD];    // 16 KB

    int tid = threadIdx.x;
    int b   = blockIdx.y;
    int i0  = blockIdx.x * TI;
    int js  = blockIdx.z;

    // phase A: gumbel-softmax rows i0..i0+15
    {
        int warp = tid >> 5, lane = tid & 31;
        #pragma unroll
        for (int rr = 0; rr < 2; rr++) {
            int r = warp * 2 + rr;
            int i = i0 + r;
            const float* elp = EL + (size_t)i * NN;
            const float* up  = UN + (size_t)i * NN;
            float xv[16];
            float mx = -1e30f;
            #pragma unroll
            for (int c = 0; c < 16; c++) {
                int j = c * 32 + lane;
                float inner = logf(up[j] + EPSF);
                float g = -__logf(-inner + EPSF);
                float x = (elp[j] + g) * TAU_INV;
                xv[c] = x;
                mx = fmaxf(mx, x);
            }
            #pragma unroll
            for (int o = 16; o > 0; o >>= 1) mx = fmaxf(mx, __shfl_xor_sync(0xffffffffu, mx, o));
            float s = 0.f;
            #pragma unroll
            for (int c = 0; c < 16; c++) { float e = __expf(xv[c] - mx); xv[c] = e; s += e; }
            #pragma unroll
            for (int o = 16; o > 0; o >>= 1) s += __shfl_xor_sync(0xffffffffu, s, o);
            float rinv = 1.0f / s;
            float* oA = out_A + ((size_t)b * NN + i) * NN;
            #pragma unroll
            for (int c = 0; c < 16; c++) {
                float a = xv[c] * rinv;
                if ((c >> 2) == js) sA[r * JR + (c & 3) * 32 + lane] = a;
                if (js == 0) oA[c * 32 + lane] = a;
            }
        }
    }
    __syncthreads();

    // phase B
    int kq = tid & 31;
    int ig = tid >> 5;
    int iA = ig * 2, iB = ig * 2 + 1;

    ulonglong2 tA = *(const ulonglong2*)&g_ti[((size_t)(b * NN + i0 + iA)) * DD + kq * 4];
    ulonglong2 tB = *(const ulonglong2*)&g_ti[((size_t)(b * NN + i0 + iB)) * DD + kq * 4];
    unsigned long long accA0 = 0ull, accA1 = 0ull, accB0 = 0ull, accB1 = 0ull;

    const float4* sb4 = (const float4*)(g_sj + ((size_t)b * NN + js * JR) * DD);

    #pragma unroll 1
    for (int t = 0; t < JR / TJ; t++) {
        #pragma unroll
        for (int q = 0; q < 4; q++)
            ((float4*)sS)[tid + q * 256] = sb4[t * (TJ * DD / 4) + tid + q * 256];
        __syncthreads();

        const float* arA = sA + iA * JR + t * TJ;
        const float* arB = sA + iB * JR + t * TJ;

        #pragma unroll 4
        for (int jj = 0; jj < TJ; jj += 2) {
            float2 avA = *(const float2*)(arA + jj);
            float2 avB = *(const float2*)(arB + jj);
            {
                ulonglong2 sv = *(const ulonglong2*)&sS[jj * DD + kq * 4];
                unsigned long long aA = bcast2(avA.x);
                unsigned long long aB = bcast2(avB.x);
                relu_mad4(accA0, accA1, sv.x, sv.y, tA.x, tA.y, aA);
                relu_mad4(accB0, accB1, sv.x, sv.y, tB.x, tB.y, aB);
            }
            {
                ulonglong2 sv = *(const ulonglong2*)&sS[(jj + 1) * DD + kq * 4];
                unsigned long long aA = bcast2(avA.y);
                unsigned long long aB = bcast2(avB.y);
                relu_mad4(accA0, accA1, sv.x, sv.y, tA.x, tA.y, aA);
                relu_mad4(accB0, accB1, sv.x, sv.y, tB.x, tB.y, aB);
            }
        }
        __syncthreads();
    }

    {
        ulonglong2 oA; oA.x = accA0; oA.y = accA1;
        ulonglong2 oB; oB.x = accB0; oB.y = accB1;
        size_t base = (((size_t)js * BB + b) * NN + i0) * DD;
        *(ulonglong2*)&g_v[base + (size_t)iA * DD + kq * 4] = oA;
        *(ulonglong2*)&g_v[base + (size_t)iB * DD + kq * 4] = oB;
    }
}

// ============ K3: tiled GEMM: out = ES + (sum_js v) @ W2 + b2 ============
// grid (2048/32, 128/32) = (64,4) = 256 blocks; micro-tile 2 rows x 2 cols (packed).
__global__ void __launch_bounds__(256) k_epi(const float* __restrict__ ES,
                                             const float* __restrict__ W2,
                                             const float* __restrict__ b2,
                                             float* __restrict__ out_state)
{
    __shared__ float sV[EBK][EBM + APAD];
    __shared__ float sW[EBK][EBN];

    int tid = threadIdx.x;
    int tx  = tid & 15;                  // cols tx*2, tx*2+1
    int ty  = tid >> 4;                  // rows ty*2, ty*2+1
    int r0  = blockIdx.x * EBM;
    int c0  = blockIdx.y * EBN;

    int lrow = tid >> 3;                 // 0..31
    int lk4  = tid & 7;                  // 0..7
    int wk   = tid >> 3;                 // 0..31
    int wc4  = tid & 7;                  // 0..7

    const size_t PSTRIDE = (size_t)BB * NN * DD;

    float4 vA, wB;
    {
        size_t off = ((size_t)(r0 + lrow)) * DD + lk4 * 4;
        float4 a = *(const float4*)&g_v[off];
        float4 c = *(const float4*)&g_v[off + PSTRIDE];
        float4 d = *(const float4*)&g_v[off + 2 * PSTRIDE];
        float4 e = *(const float4*)&g_v[off + 3 * PSTRIDE];
        a.x += c.x; a.y += c.y; a.z += c.z; a.w += c.w;
        d.x += e.x; d.y += e.y; d.z += e.z; d.w += e.w;
        a.x += d.x; a.y += d.y; a.z += d.z; a.w += d.w;
        vA = a;
        wB = *(const float4*)&W2[(size_t)wk * DD + c0 + wc4 * 4];
    }

    unsigned long long acc[2];
    acc[0] = acc[1] = 0ull;

    for (int kt = 0; kt < DD; kt += EBK) {
        if (kt) __syncthreads();
        sV[lk4 * 4 + 0][lrow] = vA.x;
        sV[lk4 * 4 + 1][lrow] = vA.y;
        sV[lk4 * 4 + 2][lrow] = vA.z;
        sV[lk4 * 4 + 3][lrow] = vA.w;
        *(float4*)&sW[wk][wc4 * 4] = wB;
        __syncthreads();

        if (kt + EBK < DD) {
            int kn = kt + EBK;
            size_t off = ((size_t)(r0 + lrow)) * DD + kn + lk4 * 4;
            float4 a = *(const float4*)&g_v[off];
            float4 c = *(const float4*)&g_v[off + PSTRIDE];
            float4 d = *(const float4*)&g_v[off + 2 * PSTRIDE];
            float4 e = *(const float4*)&g_v[off + 3 * PSTRIDE];
            a.x += c.x; a.y += c.y; a.z += c.z; a.w += c.w;
            d.x += e.x; d.y += e.y; d.z += e.z; d.w += e.w;
            a.x += d.x; a.y += d.y; a.z += d.z; a.w += d.w;
            vA = a;
            wB = *(const float4*)&W2[(size_t)(kn + wk) * DD + c0 + wc4 * 4];
        }

        #pragma unroll 8
        for (int k = 0; k < EBK; k++) {
            float2 e2 = *(const float2*)&sV[k][ty * 2];
            unsigned long long w = *(const unsigned long long*)&sW[k][tx * 2];
            fma2acc(acc[0], bcast2(e2.x), w);
            fma2acc(acc[1], bcast2(e2.y), w);
        }
    }

    float2 bias = *(const float2*)&b2[c0 + tx * 2];
    #pragma unroll
    for (int r = 0; r < 2; r++) {
        size_t row = (size_t)(r0 + ty * 2 + r);
        float2 es = *(const float2*)&ES[row * DD + c0 + tx * 2];
        float2 p  = unpack2(acc[r]);
        float2 o;
        o.x = es.x + p.x + bias.x;
        o.y = es.y + p.y + bias.y;
        *(float2*)&out_state[row * DD + c0 + tx * 2] = o;
    }
}

// ---------------- launch ----------------
extern "C" void kernel_launch(void* const* d_in, const int* in_sizes, int n_in,
                              void* d_out, int out_size)
{
    const float* ES  = (const float*)d_in[0];
    const float* Wp  = (const float*)d_in[1];
    const float* bp  = (const float*)d_in[2];
    const float* EL  = (const float*)d_in[3];
    const float* W1  = (const float*)d_in[4];
    const float* b1  = (const float*)d_in[5];
    const float* W2  = (const float*)d_in[6];
    const float* b2  = (const float*)d_in[7];
    const float* UN  = (const float*)d_in[8];

    float* out_state = (float*)d_out;
    float* out_A     = (float*)d_out + (size_t)BB * NN * DD;

    k_combine<<<DD + 1, 256>>>(Wp, bp, W1, b1);
    k_proj<<<dim3((BB * NN) / PBM, 256 / PBN), 256>>>(ES);
    k_main<<<dim3(NN / TI, BB, JS), 256>>>(EL, UN, out_A);
    k_epi<<<dim3((BB * NN) / EBM, DD / EBN), 256>>>(ES, W2, b2, out_state);
}